// round 11
// baseline (speedup 1.0000x reference)
#include <cuda_runtime.h>
#include <cuda_bf16.h>
#include <cub/cub.cuh>
#include <math_constants.h>

// FrechetSort: per row (B=4096, N=8192):
//   perturbed = scores - log(-log(gumbel_u))
//   action    = argsort(-perturbed)  (descending, stable)
//   x_r       = scores[action_r]
//   denom_r   = logsumexp(x_r .. x_{N-1})
//   log_proba = sum_r (x_r - denom_r)
// Output (float32): [action (B*N) | log_proba (B)]
//
// log = XLA:CPU GenerateVF32Log (llvm_ir_runtime), aarch64-contracted:
// Cephes coefficients, Horner fmla core, tail in XLA's association:
//   y = fma(e,q1,y);  m = fma(-0.5,z,m);  m = m + y;  m = fma(e,q2,m)
// (the -z/2 is folded into m, NOT into y — differs from Cephes source order).

static constexpr int N_COLS  = 8192;
static constexpr int BLOCK_T = 1024;
static constexpr int ITEMS   = 8;   // 1024*8 = 8192

using BlockRadixSortT = cub::BlockRadixSort<unsigned int, BLOCK_T, ITEMS, unsigned short>;

struct Smem {
    union {
        typename BlockRadixSortT::TempStorage sort;
        float scores[N_COLS];
    } u;
    float warp_red[32];
};

// XLA GenerateVF32Log, aarch64 backend contraction. Positive normal x.
__device__ __forceinline__ float xla_vf32_logf(float xin) {
    unsigned int bits = __float_as_uint(xin);
    float e = (float)((int)(bits >> 23) - 126);                    // (exp-127)+1
    float m = __uint_as_float((bits & 0x007fffffu) | 0x3f000000u); // mant | 0.5

    const float SQRTHF = 0.707106781186547524f;
    bool mask = m < SQRTHF;
    float tmp = mask ? m : 0.0f;
    m = __fadd_rn(m, -1.0f);
    e = __fadd_rn(e, mask ? -1.0f : 0.0f);
    m = __fadd_rn(m, tmp);

    float z = __fmul_rn(m, m);

    float y = 7.0376836292e-2f;
    y = __fmaf_rn(y, m, -1.1514610310e-1f);
    y = __fmaf_rn(y, m,  1.1676998740e-1f);
    y = __fmaf_rn(y, m, -1.2420140846e-1f);
    y = __fmaf_rn(y, m,  1.4249322787e-1f);
    y = __fmaf_rn(y, m, -1.6668057665e-1f);
    y = __fmaf_rn(y, m,  2.0000714765e-1f);
    y = __fmaf_rn(y, m, -2.4999993993e-1f);
    y = __fmaf_rn(y, m,  3.3333331174e-1f);
    y = __fmul_rn(y, m);
    y = __fmul_rn(y, z);

    // XLA tail association (contracted):
    y = __fmaf_rn(e, -2.12194440e-4f, y);   // y = y + e*q1
    m = __fmaf_rn(-0.5f, z, m);             // m = m - z*0.5   (fmls — into m!)
    m = __fadd_rn(m, y);                    // m = m + y
    m = __fmaf_rn(e, 0.693359375f, m);      // m = m + e*q2
    return m;
}

__device__ __forceinline__ float lae(float a, float b) {
    float mx = fmaxf(a, b);
    float mn = fminf(a, b);
    if (mn == -CUDART_INF_F) return mx;
    return mx + log1pf(expf(mn - mx));
}

__global__ __launch_bounds__(BLOCK_T, 1)
void frechet_sort_kernel(const float* __restrict__ scores,
                         const float* __restrict__ gumbel_u,
                         float* __restrict__ out,
                         int n_rows, int write_logp)
{
    extern __shared__ unsigned char smem_raw[];
    Smem& sm = *reinterpret_cast<Smem*>(smem_raw);

    const int row  = blockIdx.x;
    if (row >= n_rows) return;
    const long long base = (long long)row * N_COLS;
    const int t    = threadIdx.x;
    const int lane = t & 31;
    const int warp = t >> 5;

    // ---- 1. Load + compute keys ----
    unsigned int   keys[ITEMS];
    unsigned short vals[ITEMS];
    {
        const int i0 = t * ITEMS;
        const float4* s4 = reinterpret_cast<const float4*>(scores   + base + i0);
        const float4* g4 = reinterpret_cast<const float4*>(gumbel_u + base + i0);
        float s[ITEMS], g[ITEMS];
        float4 a0 = s4[0], a1 = s4[1];
        float4 b0 = g4[0], b1 = g4[1];
        s[0]=a0.x; s[1]=a0.y; s[2]=a0.z; s[3]=a0.w;
        s[4]=a1.x; s[5]=a1.y; s[6]=a1.z; s[7]=a1.w;
        g[0]=b0.x; g[1]=b0.y; g[2]=b0.z; g[3]=b0.w;
        g[4]=b1.x; g[5]=b1.y; g[6]=b1.z; g[7]=b1.w;
        #pragma unroll
        for (int j = 0; j < ITEMS; j++) {
            float t1 = xla_vf32_logf(g[j]);       // log(u)  (negative)
            float t3 = xla_vf32_logf(-t1);        // log(-log(u))
            float pert = __fadd_rn(s[j], -t3);    // scores + gumbel
            unsigned int m = __float_as_uint(pert);
            m = (m & 0x80000000u) ? ~m : (m | 0x80000000u);
            keys[j] = ~m;                         // ascending key == descending pert
            vals[j] = (unsigned short)(i0 + j);
        }
    }

    // ---- 2. Stable block radix sort (stability verified: R4 == R10 bitwise) ----
    BlockRadixSortT(sm.u.sort).Sort(keys, vals);
    __syncthreads();

    // ---- 3. Write action ----
    {
        const int r0 = t * ITEMS;
        float4 o0, o1;
        o0.x = (float)vals[0]; o0.y = (float)vals[1]; o0.z = (float)vals[2]; o0.w = (float)vals[3];
        o1.x = (float)vals[4]; o1.y = (float)vals[5]; o1.z = (float)vals[6]; o1.w = (float)vals[7];
        float4* o4 = reinterpret_cast<float4*>(out + base + r0);
        o4[0] = o0; o4[1] = o1;
    }

    if (!write_logp) return;

    // ---- 4. Stage scores in smem, gather x in rank order ----
    for (int i = t; i < N_COLS; i += BLOCK_T)
        sm.u.scores[i] = scores[base + i];
    __syncthreads();

    float x[ITEMS];
    #pragma unroll
    for (int j = 0; j < ITEMS; j++)
        x[j] = sm.u.scores[vals[j]];

    // ---- 5. Suffix logsumexp over ranks ----
    float lsuf[ITEMS];
    lsuf[ITEMS - 1] = x[ITEMS - 1];
    #pragma unroll
    for (int j = ITEMS - 2; j >= 0; j--)
        lsuf[j] = lae(x[j], lsuf[j + 1]);
    const float tot = lsuf[0];

    float incl = tot;
    #pragma unroll
    for (int off = 1; off < 32; off <<= 1) {
        float v = __shfl_down_sync(0xFFFFFFFFu, incl, off);
        if (lane + off < 32) incl = lae(incl, v);
    }
    if (lane == 0) sm.warp_red[warp] = incl;
    __syncthreads();
    if (warp == 0) {
        float wincl = sm.warp_red[lane];
        #pragma unroll
        for (int off = 1; off < 32; off <<= 1) {
            float v = __shfl_down_sync(0xFFFFFFFFu, wincl, off);
            if (lane + off < 32) wincl = lae(wincl, v);
        }
        float wexcl = __shfl_down_sync(0xFFFFFFFFu, wincl, 1);
        if (lane == 31) wexcl = -CUDART_INF_F;
        sm.warp_red[lane] = wexcl;
    }
    __syncthreads();

    float exclWithin = __shfl_down_sync(0xFFFFFFFFu, incl, 1);
    if (lane == 31) exclWithin = -CUDART_INF_F;
    const float sufExcl = lae(exclWithin, sm.warp_red[warp]);

    float acc = 0.0f;
    #pragma unroll
    for (int j = 0; j < ITEMS; j++)
        acc += x[j] - lae(lsuf[j], sufExcl);

    // ---- 6. Block reduce -> log_proba[row] ----
    #pragma unroll
    for (int off = 16; off > 0; off >>= 1)
        acc += __shfl_down_sync(0xFFFFFFFFu, acc, off);
    __syncthreads();
    if (lane == 0) sm.warp_red[warp] = acc;
    __syncthreads();
    if (warp == 0) {
        float v = sm.warp_red[lane];
        #pragma unroll
        for (int off = 16; off > 0; off >>= 1)
            v += __shfl_down_sync(0xFFFFFFFFu, v, off);
        if (lane == 0)
            out[(long long)n_rows * N_COLS + row] = v;
    }
}

extern "C" void kernel_launch(void* const* d_in, const int* in_sizes, int n_in,
                              void* d_out, int out_size)
{
    const float* scores   = (const float*)d_in[0];
    const float* gumbel_u = (const float*)d_in[1];
    float* out = (float*)d_out;

    const int total = in_sizes[0];
    const int n_rows = total / N_COLS;
    const int write_logp = (out_size >= total + n_rows) ? 1 : 0;

    const size_t shbytes = sizeof(Smem);
    cudaFuncSetAttribute(frechet_sort_kernel,
                         cudaFuncAttributeMaxDynamicSharedMemorySize, (int)shbytes);

    frechet_sort_kernel<<<n_rows, BLOCK_T, shbytes>>>(scores, gumbel_u, out, n_rows, write_logp);
}